// round 1
// baseline (speedup 1.0000x reference)
#include <cuda_runtime.h>

// Problem dims (fixed for this dataset entry)
#define TT 1024
#define BB 64
#define II 512
#define HH 512
#define G4 2048          // 4*H
#define MROWS 65536      // T*B

// GEMM tiling
#define BM 64
#define BN 64            // output (hy) columns per block -> 4*BN gate columns
#define BK 16
#define ASP 68           // padded smem row strides
#define BSP 260

// Scratch (device globals: no runtime allocation allowed)
__device__ float g_hh[2][BB][G4];                 // h0@w_hh^T + b_ih + b_hh, per layer
__device__ float g_hy0[(size_t)MROWS * HH];       // layer-0 output (134 MB)

__device__ __forceinline__ float sigf(float x) {
    return __fdividef(1.0f, 1.0f + __expf(-x));
}
__device__ __forceinline__ float tanhfast(float x) {
    x = fminf(fmaxf(x, -15.0f), 15.0f);
    float t = __expf(2.0f * x);
    return __fdividef(t - 1.0f, t + 1.0f);
}

// ---------------------------------------------------------------------------
// Kernel A: hh[l][b][g] = sum_k h0[l][b][k] * w_hh[g][k] + b_ih[g] + b_hh[g]
// grid (G4/256, BB), 256 threads. Tiny (67 MFLOP), not perf-critical.
// ---------------------------------------------------------------------------
__global__ void hh_kernel(const float* __restrict__ h0,
                          const float* __restrict__ w_hh,
                          const float* __restrict__ b_ih,
                          const float* __restrict__ b_hh,
                          int layer) {
    __shared__ float sh[HH];
    int b = blockIdx.y;
    const float* h0r = h0 + ((size_t)layer * BB + b) * HH;
    for (int k = threadIdx.x; k < HH; k += blockDim.x) sh[k] = h0r[k];
    __syncthreads();

    int g = blockIdx.x * blockDim.x + threadIdx.x;
    const float* w = w_hh + (size_t)g * HH;
    float acc = 0.0f;
#pragma unroll 8
    for (int k = 0; k < HH; ++k) acc = fmaf(sh[k], w[k], acc);
    g_hh[layer][b][g] = acc + b_ih[g] + b_hh[g];
}

// ---------------------------------------------------------------------------
// Kernel B: fused  gates = A @ w_ih^T (+hh)  ->  LSTM pointwise  ->  hy
// A is [MROWS, 512]; w_ih is [2048, 512]. Block computes a 64x64 hy tile,
// which requires 4 gate tiles of 64x64 (i/f/g/o at col offsets 0/512/1024/1536).
// 256 threads; each thread owns a 4x4 hy micro-tile => 64 fp32 accumulators.
// ---------------------------------------------------------------------------
__global__ __launch_bounds__(256)
void lstm_gemm_kernel(const float* __restrict__ x_in,
                      const float* __restrict__ w_ih,
                      const float* __restrict__ c0_l,   // [64,512] for this layer
                      float* __restrict__ res,          // final output region (layer 1)
                      float* __restrict__ lasth,        // [64,512] this layer
                      float* __restrict__ lastc,        // [64,512] this layer
                      int layer) {
    const float* Ap  = layer ? g_hy0 : x_in;
    float*       outp = layer ? res   : g_hy0;

    __shared__ __align__(16) float As[BK][ASP];   // k-major: As[kk][row]
    __shared__ __align__(16) float Bs[BK][BSP];   // Bs[kk][gate*64 + col]

    int tid = threadIdx.x;
    int tx = tid & 15;        // 16 col groups (4 cols each)
    int ty = tid >> 4;        // 16 row groups (4 rows each)
    int n0 = blockIdx.x * BN;
    int m0 = blockIdx.y * BM;

    float acc[4][4][4];       // [gate][ii][jj]
#pragma unroll
    for (int g = 0; g < 4; g++)
#pragma unroll
        for (int i = 0; i < 4; i++)
#pragma unroll
            for (int j = 0; j < 4; j++) acc[g][i][j] = 0.0f;

    const int ar  = tid >> 2;   // A load: row 0..63
    const int ac4 = tid & 3;    // A load: which float4 along k
    const int brr = tid >> 4;   // B load: base row 0..15
    const int bkk = tid & 15;   // B load: k within chunk

    for (int k0 = 0; k0 < II; k0 += BK) {
        // ---- global -> shared: A tile (64 x 16), float4, transposed to k-major
        float4 av = *(const float4*)(Ap + (size_t)(m0 + ar) * II + k0 + ac4 * 4);
        As[ac4 * 4 + 0][ar] = av.x;
        As[ac4 * 4 + 1][ar] = av.y;
        As[ac4 * 4 + 2][ar] = av.z;
        As[ac4 * 4 + 3][ar] = av.w;

        // ---- global -> shared: B tile (256 gate-rows x 16 k), coalesced along k
#pragma unroll
        for (int p = 0; p < 16; ++p) {
            int row  = brr + p * 16;            // 0..255
            int gate = row >> 6;
            int col  = row & 63;
            int grow = gate * 512 + n0 + col;   // row in w_ih
            Bs[bkk][row] = w_ih[(size_t)grow * 512 + k0 + bkk];
        }
        __syncthreads();

        // ---- compute
#pragma unroll
        for (int kk = 0; kk < BK; ++kk) {
            float a_[4];
#pragma unroll
            for (int i = 0; i < 4; i++) a_[i] = As[kk][ty * 4 + i];
#pragma unroll
            for (int g = 0; g < 4; g++) {
                float4 bv = *(const float4*)&Bs[kk][g * 64 + tx * 4];
#pragma unroll
                for (int i = 0; i < 4; i++) {
                    acc[g][i][0] = fmaf(a_[i], bv.x, acc[g][i][0]);
                    acc[g][i][1] = fmaf(a_[i], bv.y, acc[g][i][1]);
                    acc[g][i][2] = fmaf(a_[i], bv.z, acc[g][i][2]);
                    acc[g][i][3] = fmaf(a_[i], bv.w, acc[g][i][3]);
                }
            }
        }
        __syncthreads();
    }

    // ---- fused LSTM epilogue
#pragma unroll
    for (int i = 0; i < 4; i++) {
        int m = m0 + ty * 4 + i;
        int b = m & (BB - 1);                    // batch index (B == 64)
        const float* hhb = g_hh[layer][b];
        bool last = (m >= MROWS - BB);           // t == T-1 rows
#pragma unroll
        for (int j = 0; j < 4; j++) {
            int n = n0 + tx * 4 + j;
            float ig = acc[0][i][j] + hhb[n];
            float fg = acc[1][i][j] + hhb[512 + n];
            float gg = acc[2][i][j] + hhb[1024 + n];
            float og = acc[3][i][j] + hhb[1536 + n];
            float cy = sigf(fg) * c0_l[b * 512 + n] + sigf(ig) * tanhfast(gg);
            float hy = sigf(og) * tanhfast(cy);
            outp[(size_t)m * 512 + n] = hy;
            if (last) {
                lasth[b * 512 + n] = hy;
                lastc[b * 512 + n] = cy;
            }
        }
    }
}

// ---------------------------------------------------------------------------
extern "C" void kernel_launch(void* const* d_in, const int* in_sizes, int n_in,
                              void* d_out, int out_size) {
    const float* x      = (const float*)d_in[0];
    const float* h0     = (const float*)d_in[1];
    const float* c0     = (const float*)d_in[2];
    const float* w_ih_0 = (const float*)d_in[3];
    const float* w_hh_0 = (const float*)d_in[4];
    const float* b_ih_0 = (const float*)d_in[5];
    const float* b_hh_0 = (const float*)d_in[6];
    const float* w_ih_1 = (const float*)d_in[7];
    const float* w_hh_1 = (const float*)d_in[8];
    const float* b_ih_1 = (const float*)d_in[9];
    const float* b_hh_1 = (const float*)d_in[10];
    (void)in_sizes; (void)n_in; (void)out_size;

    float* out = (float*)d_out;
    float* res = out;                                  // [65536, 512]
    float* lh  = out + (size_t)MROWS * HH;             // [2, 64, 512]
    float* lc  = lh + 2 * BB * HH;                     // [2, 64, 512]

    dim3 hgrid(G4 / 256, BB);
    hh_kernel<<<hgrid, 256>>>(h0, w_hh_0, b_ih_0, b_hh_0, 0);
    hh_kernel<<<hgrid, 256>>>(h0, w_hh_1, b_ih_1, b_hh_1, 1);

    dim3 ggrid(HH / BN, MROWS / BM);  // (8, 1024)
    // layer 0: x -> g_hy0
    lstm_gemm_kernel<<<ggrid, 256>>>(x, w_ih_0, c0, res,
                                     lh, lc, 0);
    // layer 1: g_hy0 -> res
    lstm_gemm_kernel<<<ggrid, 256>>>(x, w_ih_1, c0 + BB * HH, res,
                                     lh + BB * HH, lc + BB * HH, 1);
}

// round 3
// speedup vs baseline: 1.8512x; 1.8512x over previous
#include <cuda_runtime.h>
#include <cuda_bf16.h>
#include <cstdint>

// ---------------- problem dims ----------------
#define MROWS 65536     // T*B
#define IIK   512       // K
#define G4    2048      // 4*H
#define BB    64        // batch
#define HHH   512       // H

// ---------------- tiling ----------------
#define TM   128        // M rows per CTA
#define TNH  32         // hy cols per CTA -> 128 gate cols
#define KC   32         // K chunk
#define NIT  16         // 512/32

// smem: stage = A_hi(10240) A_lo(10240) B_hi(10240) B_lo(10240) = 40960 B
// rows padded: 32 bf16 data + 8 pad = 40 elems = 80 B stride (16B aligned, LDSM conflict-free)
#define STG   40960
#define SMEMT (2*STG)   // 81920; epilogue reuses as 128x132 f32 (67584 B)

// ---------------- device scratch (no runtime alloc) ----------------
__device__ __align__(16) __nv_bfloat16 g_A0_hi[(size_t)MROWS * IIK];
__device__ __align__(16) __nv_bfloat16 g_A0_lo[(size_t)MROWS * IIK];
__device__ __align__(16) __nv_bfloat16 g_A1_hi[(size_t)MROWS * IIK];
__device__ __align__(16) __nv_bfloat16 g_A1_lo[(size_t)MROWS * IIK];
__device__ __align__(16) __nv_bfloat16 g_W_hi[2][G4 * IIK];
__device__ __align__(16) __nv_bfloat16 g_W_lo[2][G4 * IIK];
__device__ float g_hh[2][BB][G4];

// ---------------- asm helpers (all plain sm_80/90 PTX, no 'a' features) ----
__device__ __forceinline__ uint32_t smem_to_u32(const void* p) {
    uint32_t a;
    asm("{ .reg .u64 t; cvta.to.shared.u64 t, %1; cvt.u32.u64 %0, t; }"
        : "=r"(a) : "l"(p));
    return a;
}
#define CP_ASYNC16(s, g) \
    asm volatile("cp.async.cg.shared.global [%0], [%1], 16;" :: "r"(s), "l"(g))
#define CP_COMMIT() asm volatile("cp.async.commit_group;" ::: "memory")
#define CP_WAIT1()  asm volatile("cp.async.wait_group 1;" ::: "memory")
#define CP_WAIT0()  asm volatile("cp.async.wait_group 0;" ::: "memory")

#define LDSM4(r, addr) \
    asm volatile("ldmatrix.sync.aligned.m8n8.x4.shared.b16 {%0,%1,%2,%3}, [%4];" \
        : "=r"((r)[0]), "=r"((r)[1]), "=r"((r)[2]), "=r"((r)[3]) : "r"(addr))

__device__ __forceinline__ void mma_bf16(float* c, const unsigned* a, const unsigned* b) {
    asm volatile(
        "mma.sync.aligned.m16n8k16.row.col.f32.bf16.bf16.f32 "
        "{%0,%1,%2,%3}, {%4,%5,%6,%7}, {%8,%9}, {%0,%1,%2,%3};"
        : "+f"(c[0]), "+f"(c[1]), "+f"(c[2]), "+f"(c[3])
        : "r"(a[0]), "r"(a[1]), "r"(a[2]), "r"(a[3]), "r"(b[0]), "r"(b[1]));
}

// ---------------- activations ----------------
__device__ __forceinline__ float sigf(float x) {
    return __fdividef(1.0f, 1.0f + __expf(-x));
}
__device__ __forceinline__ float tanhf_(float x) {
    return 2.0f * sigf(2.0f * x) - 1.0f;
}

// ---------------------------------------------------------------------------
// fp32 -> bf16 hi/lo splitter.  mode: 0=x->A0, 1=w_ih_0->W[0], 2=w_ih_1->W[1]
// ---------------------------------------------------------------------------
__global__ void cvt_split(const float* __restrict__ src, int n4, int mode) {
    int i = blockIdx.x * blockDim.x + threadIdx.x;
    if (i >= n4) return;
    __nv_bfloat16 *hi, *lo;
    if (mode == 0)      { hi = g_A0_hi;   lo = g_A0_lo; }
    else if (mode == 1) { hi = g_W_hi[0]; lo = g_W_lo[0]; }
    else                { hi = g_W_hi[1]; lo = g_W_lo[1]; }
    float4 v = ((const float4*)src)[i];
    __nv_bfloat16 hx = __float2bfloat16(v.x);
    __nv_bfloat16 hy = __float2bfloat16(v.y);
    __nv_bfloat16 hz = __float2bfloat16(v.z);
    __nv_bfloat16 hw = __float2bfloat16(v.w);
    __nv_bfloat16 lx = __float2bfloat16(v.x - __bfloat162float(hx));
    __nv_bfloat16 ly = __float2bfloat16(v.y - __bfloat162float(hy));
    __nv_bfloat16 lz = __float2bfloat16(v.z - __bfloat162float(hz));
    __nv_bfloat16 lw = __float2bfloat16(v.w - __bfloat162float(hw));
    ((__nv_bfloat162*)hi)[2*i]   = __nv_bfloat162(hx, hy);
    ((__nv_bfloat162*)hi)[2*i+1] = __nv_bfloat162(hz, hw);
    ((__nv_bfloat162*)lo)[2*i]   = __nv_bfloat162(lx, ly);
    ((__nv_bfloat162*)lo)[2*i+1] = __nv_bfloat162(lz, lw);
}

// ---------------------------------------------------------------------------
// hh[l][b][g] = h0[l][b] . w_hh[g] + b_ih[g] + b_hh[g]   (tiny, fp32 SIMT)
// ---------------------------------------------------------------------------
__global__ void hh_kernel(const float* __restrict__ h0,
                          const float* __restrict__ w_hh,
                          const float* __restrict__ b_ih,
                          const float* __restrict__ b_hh,
                          int layer) {
    __shared__ float sh[HHH];
    int b = blockIdx.y;
    const float* h0r = h0 + ((size_t)layer * BB + b) * HHH;
    for (int k = threadIdx.x; k < HHH; k += blockDim.x) sh[k] = h0r[k];
    __syncthreads();
    int g = blockIdx.x * blockDim.x + threadIdx.x;
    const float* w = w_hh + (size_t)g * HHH;
    float acc = 0.0f;
#pragma unroll 8
    for (int k = 0; k < HHH; ++k) acc = fmaf(sh[k], w[k], acc);
    g_hh[layer][b][g] = acc + b_ih[g] + b_hh[g];
}

// ---------------------------------------------------------------------------
// Main HMMA LSTM layer kernel.  grid (16, 512), 256 threads.
// Gate-interleaved B rows: smem B row n <-> w_ih row (n%4)*512 + n0h + n/4.
// ---------------------------------------------------------------------------
__global__ void __launch_bounds__(256, 1)
lstm_mma_kernel(const float* __restrict__ c0,
                float* __restrict__ res,
                float* __restrict__ lh,
                float* __restrict__ lc,
                int layer) {
    extern __shared__ __align__(16) char sm[];
    const uint32_t smem_u32 = smem_to_u32(sm);
    const int tid  = threadIdx.x;
    const int wid  = tid >> 5;
    const int lane = tid & 31;
    const int n0h  = blockIdx.x * TNH;
    const int m0   = blockIdx.y * TM;

    const __nv_bfloat16* __restrict__ Ah = layer ? g_A1_hi : g_A0_hi;
    const __nv_bfloat16* __restrict__ Al = layer ? g_A1_lo : g_A0_lo;
    const __nv_bfloat16* __restrict__ Wh = g_W_hi[layer];
    const __nv_bfloat16* __restrict__ Wl = g_W_lo[layer];
    const float* __restrict__ hh_l = &g_hh[layer][0][0];
    const float* __restrict__ c0_l = c0 + (size_t)layer * BB * HHH;
    float* __restrict__ lasth = lh + (size_t)layer * BB * HHH;
    float* __restrict__ lastc = lc + (size_t)layer * BB * HHH;

    // loader per-thread invariants: 512 granules per operand, 2 per thread
    const int rA  = tid >> 2;     // rows rA and rA+64
    const int kc8 = tid & 3;      // 16B granule along k

    // ldmatrix per-lane invariants
    const int wm = wid & 3;       // M sub-tile (32 rows)
    const int wn = wid >> 2;      // N half (64 gate cols)
    const uint32_t aRowOff = (uint32_t)(lane & 15) * 80;
    const uint32_t aKoff   = (uint32_t)((lane >> 4) & 1) * 16;
    const uint32_t bRowOff = (uint32_t)(((lane >> 4) & 1) * 8 + (lane & 7)) * 80;
    const uint32_t bKoff   = (uint32_t)((lane >> 3) & 1) * 16;

    float acc[2][8][4];
#pragma unroll
    for (int mt = 0; mt < 2; ++mt)
#pragma unroll
        for (int nb = 0; nb < 8; ++nb)
#pragma unroll
            for (int q = 0; q < 4; ++q) acc[mt][nb][q] = 0.0f;

    // ---- stage loader (lambda-free) ----
#define LOAD_STAGE(CHUNK)                                                      \
    do {                                                                       \
        const int _k0 = (CHUNK) * KC;                                          \
        const uint32_t _sb = smem_u32 + ((CHUNK) & 1) * STG;                   \
        _Pragma("unroll")                                                      \
        for (int rep = 0; rep < 2; ++rep) {                                    \
            const int row = rA + rep * 64;                                     \
            const uint32_t so = _sb + row * 80 + kc8 * 16;                     \
            const size_t ga = (size_t)(m0 + row) * IIK + _k0 + kc8 * 8;        \
            CP_ASYNC16(so,          Ah + ga);                                  \
            CP_ASYNC16(so + 10240,  Al + ga);                                  \
            const int wrow = (row & 3) * 512 + n0h + (row >> 2);               \
            const size_t gb = (size_t)wrow * IIK + _k0 + kc8 * 8;              \
            CP_ASYNC16(so + 20480,  Wh + gb);                                  \
            CP_ASYNC16(so + 30720,  Wl + gb);                                  \
        }                                                                      \
        CP_COMMIT();                                                           \
    } while (0)

    LOAD_STAGE(0);

    for (int it = 0; it < NIT; ++it) {
        if (it + 1 < NIT) { LOAD_STAGE(it + 1); CP_WAIT1(); }
        else              { CP_WAIT0(); }
        __syncthreads();

        const uint32_t sb = smem_u32 + (it & 1) * STG;
#pragma unroll
        for (int ks = 0; ks < 2; ++ks) {
            unsigned ah[2][4], al[2][4];
#pragma unroll
            for (int mt = 0; mt < 2; ++mt) {
                uint32_t aa = sb + (uint32_t)(wm * 32 + mt * 16) * 80
                              + aRowOff + ks * 32 + aKoff;
                LDSM4(ah[mt], aa);
                LDSM4(al[mt], aa + 10240);
            }
            unsigned bh[4][4], bl[4][4];
#pragma unroll
            for (int p = 0; p < 4; ++p) {
                uint32_t ba = sb + 20480 + (uint32_t)(wn * 64 + p * 16) * 80
                              + bRowOff + ks * 32 + bKoff;
                LDSM4(bh[p], ba);
                LDSM4(bl[p], ba + 10240);
            }
#pragma unroll
            for (int mt = 0; mt < 2; ++mt)
#pragma unroll
                for (int p = 0; p < 4; ++p) {
                    mma_bf16(acc[mt][2*p],   ah[mt], &bh[p][0]);
                    mma_bf16(acc[mt][2*p+1], ah[mt], &bh[p][2]);
                    mma_bf16(acc[mt][2*p],   al[mt], &bh[p][0]);
                    mma_bf16(acc[mt][2*p+1], al[mt], &bh[p][2]);
                    mma_bf16(acc[mt][2*p],   ah[mt], &bl[p][0]);
                    mma_bf16(acc[mt][2*p+1], ah[mt], &bl[p][2]);
                }
        }
        __syncthreads();
    }

    // ---- epilogue: dump gate tile (128 x 128 f32, stride 132) into smem ----
    float* Gs = (float*)sm;
#pragma unroll
    for (int mt = 0; mt < 2; ++mt) {
        const int r0 = wm * 32 + mt * 16 + (lane >> 2);
#pragma unroll
        for (int nb = 0; nb < 8; ++nb) {
            const int cb = wn * 64 + nb * 8 + (lane & 3) * 2;
            Gs[r0 * 132 + cb]           = acc[mt][nb][0];
            Gs[r0 * 132 + cb + 1]       = acc[mt][nb][1];
            Gs[(r0 + 8) * 132 + cb]     = acc[mt][nb][2];
            Gs[(r0 + 8) * 132 + cb + 1] = acc[mt][nb][3];
        }
    }
    __syncthreads();

    // ---- fused LSTM pointwise (128 rows x 32 hy cols) ----
#pragma unroll
    for (int e = tid; e < TM * TNH; e += 256) {
        const int row = e >> 5;
        const int col = e & 31;
        const int m   = m0 + row;
        const int b   = m & (BB - 1);
        const int nh  = n0h + col;
        const float* hhb = hh_l + (size_t)b * G4;
        float ig = Gs[row * 132 + col * 4 + 0] + hhb[nh];
        float fg = Gs[row * 132 + col * 4 + 1] + hhb[512 + nh];
        float gg = Gs[row * 132 + col * 4 + 2] + hhb[1024 + nh];
        float og = Gs[row * 132 + col * 4 + 3] + hhb[1536 + nh];
        float cy = sigf(fg) * c0_l[(size_t)b * HHH + nh] + sigf(ig) * tanhf_(gg);
        float hy = sigf(og) * tanhf_(cy);
        if (layer == 0) {
            __nv_bfloat16 h = __float2bfloat16(hy);
            __nv_bfloat16 l = __float2bfloat16(hy - __bfloat162float(h));
            g_A1_hi[(size_t)m * HHH + nh] = h;
            g_A1_lo[(size_t)m * HHH + nh] = l;
        } else {
            res[(size_t)m * HHH + nh] = hy;
        }
        if (m >= MROWS - BB) {
            lasth[(size_t)b * HHH + nh] = hy;
            lastc[(size_t)b * HHH + nh] = cy;
        }
    }
}

// ---------------------------------------------------------------------------
extern "C" void kernel_launch(void* const* d_in, const int* in_sizes, int n_in,
                              void* d_out, int out_size) {
    const float* x      = (const float*)d_in[0];
    const float* h0     = (const float*)d_in[1];
    const float* c0     = (const float*)d_in[2];
    const float* w_ih_0 = (const float*)d_in[3];
    const float* w_hh_0 = (const float*)d_in[4];
    const float* b_ih_0 = (const float*)d_in[5];
    const float* b_hh_0 = (const float*)d_in[6];
    const float* w_ih_1 = (const float*)d_in[7];
    const float* w_hh_1 = (const float*)d_in[8];
    const float* b_ih_1 = (const float*)d_in[9];
    const float* b_hh_1 = (const float*)d_in[10];
    (void)in_sizes; (void)n_in; (void)out_size;

    float* out = (float*)d_out;
    float* res = out;                                  // [65536, 512]
    float* lh  = out + (size_t)MROWS * HHH;            // [2, 64, 512]
    float* lc  = lh + 2 * BB * HHH;                    // [2, 64, 512]

    cudaFuncSetAttribute(lstm_mma_kernel,
                         cudaFuncAttributeMaxDynamicSharedMemorySize, SMEMT);

    // precision-split pre-pass
    cvt_split<<<(MROWS * IIK / 4 + 255) / 256, 256>>>(x, MROWS * IIK / 4, 0);
    cvt_split<<<(G4 * IIK / 4 + 255) / 256, 256>>>(w_ih_0, G4 * IIK / 4, 1);
    cvt_split<<<(G4 * IIK / 4 + 255) / 256, 256>>>(w_ih_1, G4 * IIK / 4, 2);

    // hh precompute
    dim3 hgrid(G4 / 256, BB);
    hh_kernel<<<hgrid, 256>>>(h0, w_hh_0, b_ih_0, b_hh_0, 0);
    hh_kernel<<<hgrid, 256>>>(h0, w_hh_1, b_ih_1, b_hh_1, 1);

    // HMMA layers
    dim3 ggrid(HHH / TNH, MROWS / TM);   // (16, 512)
    lstm_mma_kernel<<<ggrid, 256, SMEMT>>>(c0, res, lh, lc, 0);
    lstm_mma_kernel<<<ggrid, 256, SMEMT>>>(c0, res, lh, lc, 1);
}

// round 4
// speedup vs baseline: 2.7962x; 1.5105x over previous
#include <cuda_runtime.h>
#include <cuda_bf16.h>
#include <cstdint>

// ---------------- problem dims ----------------
#define MROWS 65536     // T*B
#define IIK   512       // K
#define G4    2048      // 4*H
#define BB    64        // batch
#define HHH   512       // H

// ---------------- tiling ----------------
#define TM   128        // M rows per CTA
#define TNH  32         // hy cols per CTA -> 128 gate cols
#define KC   32         // K chunk
#define NIT  16         // 512/32

// smem: stage = A_hi(10240) A_lo(10240) B_hi(10240) B_lo(10240) = 40960 B
// rows padded: 32 bf16 data + 8 pad = 40 elems = 80 B stride
#define STG   40960
#define SMEMT (2*STG)   // 81920; epilogue reuses as 128x132 f32 (67584 B)

// ---------------- device scratch (no runtime alloc) ----------------
__device__ __align__(16) __nv_bfloat16 g_A0_hi[(size_t)MROWS * IIK];
__device__ __align__(16) __nv_bfloat16 g_A0_lo[(size_t)MROWS * IIK];
__device__ __align__(16) __nv_bfloat16 g_A1_hi[(size_t)MROWS * IIK];
__device__ __align__(16) __nv_bfloat16 g_A1_lo[(size_t)MROWS * IIK];
__device__ __align__(16) __nv_bfloat16 g_W_hi[2][G4 * IIK];
__device__ __align__(16) __nv_bfloat16 g_W_lo[2][G4 * IIK];
__device__ float g_hh[2][BB][G4];

// ---------------- asm helpers (plain sm_80/90 PTX only) ----------------
__device__ __forceinline__ uint32_t smem_to_u32(const void* p) {
    uint32_t a;
    asm("{ .reg .u64 t; cvta.to.shared.u64 t, %1; cvt.u32.u64 %0, t; }"
        : "=r"(a) : "l"(p));
    return a;
}
#define CP_ASYNC16(s, g) \
    asm volatile("cp.async.cg.shared.global [%0], [%1], 16;" :: "r"(s), "l"(g))
#define CP_COMMIT() asm volatile("cp.async.commit_group;" ::: "memory")
#define CP_WAIT1()  asm volatile("cp.async.wait_group 1;" ::: "memory")
#define CP_WAIT0()  asm volatile("cp.async.wait_group 0;" ::: "memory")

#define LDSM4(r, addr) \
    asm volatile("ldmatrix.sync.aligned.m8n8.x4.shared.b16 {%0,%1,%2,%3}, [%4];" \
        : "=r"((r)[0]), "=r"((r)[1]), "=r"((r)[2]), "=r"((r)[3]) : "r"(addr))

__device__ __forceinline__ void mma_bf16(float* c, const unsigned* a, const unsigned* b) {
    asm volatile(
        "mma.sync.aligned.m16n8k16.row.col.f32.bf16.bf16.f32 "
        "{%0,%1,%2,%3}, {%4,%5,%6,%7}, {%8,%9}, {%0,%1,%2,%3};"
        : "+f"(c[0]), "+f"(c[1]), "+f"(c[2]), "+f"(c[3])
        : "r"(a[0]), "r"(a[1]), "r"(a[2]), "r"(a[3]), "r"(b[0]), "r"(b[1]));
}

// ---------------- activations ----------------
__device__ __forceinline__ float sigf(float x) {
    return __fdividef(1.0f, 1.0f + __expf(-x));
}
__device__ __forceinline__ float tanhf_(float x) {
    return 2.0f * sigf(2.0f * x) - 1.0f;
}

// ---------------------------------------------------------------------------
// fp32 -> bf16 hi/lo splitter.  mode: 0=x->A0, 1=w_ih_0->W[0], 2=w_ih_1->W[1]
// ---------------------------------------------------------------------------
__global__ void cvt_split(const float* __restrict__ src, int n4, int mode) {
    int i = blockIdx.x * blockDim.x + threadIdx.x;
    if (i >= n4) return;
    __nv_bfloat16 *hi, *lo;
    if (mode == 0)      { hi = g_A0_hi;   lo = g_A0_lo; }
    else if (mode == 1) { hi = g_W_hi[0]; lo = g_W_lo[0]; }
    else                { hi = g_W_hi[1]; lo = g_W_lo[1]; }
    float4 v = ((const float4*)src)[i];
    __nv_bfloat16 hx = __float2bfloat16(v.x);
    __nv_bfloat16 hy = __float2bfloat16(v.y);
    __nv_bfloat16 hz = __float2bfloat16(v.z);
    __nv_bfloat16 hw = __float2bfloat16(v.w);
    __nv_bfloat16 lx = __float2bfloat16(v.x - __bfloat162float(hx));
    __nv_bfloat16 ly = __float2bfloat16(v.y - __bfloat162float(hy));
    __nv_bfloat16 lz = __float2bfloat16(v.z - __bfloat162float(hz));
    __nv_bfloat16 lw = __float2bfloat16(v.w - __bfloat162float(hw));
    ((__nv_bfloat162*)hi)[2*i]   = __nv_bfloat162(hx, hy);
    ((__nv_bfloat162*)hi)[2*i+1] = __nv_bfloat162(hz, hw);
    ((__nv_bfloat162*)lo)[2*i]   = __nv_bfloat162(lx, ly);
    ((__nv_bfloat162*)lo)[2*i+1] = __nv_bfloat162(lz, lw);
}

// ---------------------------------------------------------------------------
// hh[l][b][g] = h0[l][b] . w_hh[g] + b_ih[g] + b_hh[g]
// Proper tiled GEMM: grid (G4/64, 2 layers), 256 thr, 64x64 tile, w read ONCE.
// ---------------------------------------------------------------------------
__global__ void __launch_bounds__(256)
hh_kernel(const float* __restrict__ h0,
          const float* __restrict__ w_hh_0, const float* __restrict__ w_hh_1,
          const float* __restrict__ b_ih_0, const float* __restrict__ b_hh_0,
          const float* __restrict__ b_ih_1, const float* __restrict__ b_hh_1) {
    const int layer = blockIdx.y;
    const int g0 = blockIdx.x * 64;
    const float* __restrict__ w  = layer ? w_hh_1 : w_hh_0;
    const float* __restrict__ bi = layer ? b_ih_1 : b_ih_0;
    const float* __restrict__ bh = layer ? b_hh_1 : b_hh_0;

    __shared__ __align__(16) float As[KC][68];   // [k][b]
    __shared__ __align__(16) float Bs[KC][68];   // [k][g]

    const int tid = threadIdx.x;
    const int tx = tid & 15;        // g groups
    const int ty = tid >> 4;        // b groups
    const int lr  = tid >> 3;       // load row 0..31 (of 64, two reps)
    const int lk4 = tid & 7;        // float4 along k

    float acc[4][4];
#pragma unroll
    for (int i = 0; i < 4; i++)
#pragma unroll
        for (int j = 0; j < 4; j++) acc[i][j] = 0.0f;

    for (int k0 = 0; k0 < IIK; k0 += KC) {
#pragma unroll
        for (int rep = 0; rep < 2; ++rep) {
            const int row = lr + rep * 32;
            float4 av = *(const float4*)(h0 + ((size_t)layer * BB + row) * IIK + k0 + lk4 * 4);
            As[lk4 * 4 + 0][row] = av.x;
            As[lk4 * 4 + 1][row] = av.y;
            As[lk4 * 4 + 2][row] = av.z;
            As[lk4 * 4 + 3][row] = av.w;
            float4 bv = *(const float4*)(w + (size_t)(g0 + row) * IIK + k0 + lk4 * 4);
            Bs[lk4 * 4 + 0][row] = bv.x;
            Bs[lk4 * 4 + 1][row] = bv.y;
            Bs[lk4 * 4 + 2][row] = bv.z;
            Bs[lk4 * 4 + 3][row] = bv.w;
        }
        __syncthreads();
#pragma unroll
        for (int k = 0; k < KC; ++k) {
            float a_[4], b_[4];
#pragma unroll
            for (int i = 0; i < 4; i++) a_[i] = As[k][ty * 4 + i];
#pragma unroll
            for (int j = 0; j < 4; j++) b_[j] = Bs[k][tx * 4 + j];
#pragma unroll
            for (int i = 0; i < 4; i++)
#pragma unroll
                for (int j = 0; j < 4; j++) acc[i][j] = fmaf(a_[i], b_[j], acc[i][j]);
        }
        __syncthreads();
    }
#pragma unroll
    for (int i = 0; i < 4; i++) {
        const int b = ty * 4 + i;
#pragma unroll
        for (int j = 0; j < 4; j++) {
            const int g = g0 + tx * 4 + j;
            g_hh[layer][b][g] = acc[i][j] + bi[g] + bh[g];
        }
    }
}

// ---------------------------------------------------------------------------
// Main HMMA LSTM layer kernel.  grid (16, 512), 256 threads, 2 CTAs/SM.
// Gate-interleaved B rows: smem B row n <-> w_ih row (n%4)*512 + n0h + n/4.
// ---------------------------------------------------------------------------
__global__ void __launch_bounds__(256, 2)
lstm_mma_kernel(const float* __restrict__ c0,
                float* __restrict__ res,
                float* __restrict__ lh,
                float* __restrict__ lc,
                int layer) {
    extern __shared__ __align__(16) char sm[];
    const uint32_t smem_u32 = smem_to_u32(sm);
    const int tid  = threadIdx.x;
    const int wid  = tid >> 5;
    const int lane = tid & 31;
    const int n0h  = blockIdx.x * TNH;
    const int m0   = blockIdx.y * TM;

    const __nv_bfloat16* __restrict__ Ah = layer ? g_A1_hi : g_A0_hi;
    const __nv_bfloat16* __restrict__ Al = layer ? g_A1_lo : g_A0_lo;
    const __nv_bfloat16* __restrict__ Wh = g_W_hi[layer];
    const __nv_bfloat16* __restrict__ Wl = g_W_lo[layer];
    const float* __restrict__ hh_l = &g_hh[layer][0][0];
    const float* __restrict__ c0_l = c0 + (size_t)layer * BB * HHH;
    float* __restrict__ lasth = lh + (size_t)layer * BB * HHH;
    float* __restrict__ lastc = lc + (size_t)layer * BB * HHH;

    // loader invariants
    const int rA  = tid >> 2;     // rows rA and rA+64
    const int kc8 = tid & 3;      // 16B granule along k

    // ldmatrix invariants
    const int wm = wid & 3;       // M sub-tile (32 rows)
    const int wn = wid >> 2;      // N half (64 gate cols)
    const uint32_t aRowOff = (uint32_t)(lane & 15) * 80;
    const uint32_t aKoff   = (uint32_t)((lane >> 4) & 1) * 16;
    const uint32_t bRowOff = (uint32_t)(((lane >> 4) & 1) * 8 + (lane & 7)) * 80;
    const uint32_t bKoff   = (uint32_t)((lane >> 3) & 1) * 16;

    float acc[2][8][4];
#pragma unroll
    for (int mt = 0; mt < 2; ++mt)
#pragma unroll
        for (int nb = 0; nb < 8; ++nb)
#pragma unroll
            for (int q = 0; q < 4; ++q) acc[mt][nb][q] = 0.0f;

#define LOAD_STAGE(CHUNK)                                                      \
    do {                                                                       \
        const int _k0 = (CHUNK) * KC;                                          \
        const uint32_t _sb = smem_u32 + ((CHUNK) & 1) * STG;                   \
        _Pragma("unroll")                                                      \
        for (int rep = 0; rep < 2; ++rep) {                                    \
            const int row = rA + rep * 64;                                     \
            const uint32_t so = _sb + row * 80 + kc8 * 16;                     \
            const size_t ga = (size_t)(m0 + row) * IIK + _k0 + kc8 * 8;        \
            CP_ASYNC16(so,          Ah + ga);                                  \
            CP_ASYNC16(so + 10240,  Al + ga);                                  \
            const int wrow = (row & 3) * 512 + n0h + (row >> 2);               \
            const size_t gb = (size_t)wrow * IIK + _k0 + kc8 * 8;              \
            CP_ASYNC16(so + 20480,  Wh + gb);                                  \
            CP_ASYNC16(so + 30720,  Wl + gb);                                  \
        }                                                                      \
        CP_COMMIT();                                                           \
    } while (0)

    LOAD_STAGE(0);

    for (int it = 0; it < NIT; ++it) {
        if (it + 1 < NIT) { LOAD_STAGE(it + 1); CP_WAIT1(); }
        else              { CP_WAIT0(); }
        __syncthreads();

        const uint32_t sb = smem_u32 + (it & 1) * STG;
#pragma unroll
        for (int ks = 0; ks < 2; ++ks) {
            unsigned ah[2][4], al[2][4];
#pragma unroll
            for (int mt = 0; mt < 2; ++mt) {
                uint32_t aa = sb + (uint32_t)(wm * 32 + mt * 16) * 80
                              + aRowOff + ks * 32 + aKoff;
                LDSM4(ah[mt], aa);
                LDSM4(al[mt], aa + 10240);
            }
            // process B in pairs of 16-col sub-tiles to cap live registers
#pragma unroll
            for (int ph = 0; ph < 2; ++ph) {
                unsigned bh[2][4], bl[2][4];
#pragma unroll
                for (int p2 = 0; p2 < 2; ++p2) {
                    uint32_t ba = sb + 20480
                                  + (uint32_t)(wn * 64 + (ph * 2 + p2) * 16) * 80
                                  + bRowOff + ks * 32 + bKoff;
                    LDSM4(bh[p2], ba);
                    LDSM4(bl[p2], ba + 10240);
                }
#pragma unroll
                for (int mt = 0; mt < 2; ++mt)
#pragma unroll
                    for (int p2 = 0; p2 < 2; ++p2) {
                        const int p = ph * 2 + p2;
                        mma_bf16(acc[mt][2*p],   ah[mt], &bh[p2][0]);
                        mma_bf16(acc[mt][2*p+1], ah[mt], &bh[p2][2]);
                        mma_bf16(acc[mt][2*p],   al[mt], &bh[p2][0]);
                        mma_bf16(acc[mt][2*p+1], al[mt], &bh[p2][2]);
                        mma_bf16(acc[mt][2*p],   ah[mt], &bl[p2][0]);
                        mma_bf16(acc[mt][2*p+1], ah[mt], &bl[p2][2]);
                    }
            }
        }
        __syncthreads();
    }

    // ---- epilogue: dump gate tile (128 x 128 f32, stride 132) into smem ----
    float* Gs = (float*)sm;
#pragma unroll
    for (int mt = 0; mt < 2; ++mt) {
        const int r0 = wm * 32 + mt * 16 + (lane >> 2);
#pragma unroll
        for (int nb = 0; nb < 8; ++nb) {
            const int cb = wn * 64 + nb * 8 + (lane & 3) * 2;
            Gs[r0 * 132 + cb]           = acc[mt][nb][0];
            Gs[r0 * 132 + cb + 1]       = acc[mt][nb][1];
            Gs[(r0 + 8) * 132 + cb]     = acc[mt][nb][2];
            Gs[(r0 + 8) * 132 + cb + 1] = acc[mt][nb][3];
        }
    }
    __syncthreads();

    // ---- fused LSTM pointwise: 128 rows x 16 col-pairs per CTA ----
    for (int e = tid; e < TM * (TNH / 2); e += 256) {
        const int row = e >> 4;
        const int c2  = e & 15;
        const int m   = m0 + row;
        const int b   = m & (BB - 1);
        const int nh  = n0h + c2 * 2;
        const float* hhb = hh_l + (size_t)b * G4;
        float hy2[2], cy2[2];
#pragma unroll
        for (int u = 0; u < 2; ++u) {
            const int col = c2 * 2 + u;
            float ig = Gs[row * 132 + col * 4 + 0] + hhb[nh + u];
            float fg = Gs[row * 132 + col * 4 + 1] + hhb[512 + nh + u];
            float gg = Gs[row * 132 + col * 4 + 2] + hhb[1024 + nh + u];
            float og = Gs[row * 132 + col * 4 + 3] + hhb[1536 + nh + u];
            float cy = sigf(fg) * c0_l[(size_t)b * HHH + nh + u] + sigf(ig) * tanhf_(gg);
            cy2[u] = cy;
            hy2[u] = sigf(og) * tanhf_(cy);
        }
        if (layer == 0) {
            __nv_bfloat16 h0b = __float2bfloat16(hy2[0]);
            __nv_bfloat16 h1b = __float2bfloat16(hy2[1]);
            __nv_bfloat16 l0b = __float2bfloat16(hy2[0] - __bfloat162float(h0b));
            __nv_bfloat16 l1b = __float2bfloat16(hy2[1] - __bfloat162float(h1b));
            *(__nv_bfloat162*)(g_A1_hi + (size_t)m * HHH + nh) = __nv_bfloat162(h0b, h1b);
            *(__nv_bfloat162*)(g_A1_lo + (size_t)m * HHH + nh) = __nv_bfloat162(l0b, l1b);
        } else {
            *(float2*)(res + (size_t)m * HHH + nh) = make_float2(hy2[0], hy2[1]);
        }
        if (m >= MROWS - BB) {
            *(float2*)(lasth + (size_t)b * HHH + nh) = make_float2(hy2[0], hy2[1]);
            *(float2*)(lastc + (size_t)b * HHH + nh) = make_float2(cy2[0], cy2[1]);
        }
    }
}

// ---------------------------------------------------------------------------
extern "C" void kernel_launch(void* const* d_in, const int* in_sizes, int n_in,
                              void* d_out, int out_size) {
    const float* x      = (const float*)d_in[0];
    const float* h0     = (const float*)d_in[1];
    const float* c0     = (const float*)d_in[2];
    const float* w_ih_0 = (const float*)d_in[3];
    const float* w_hh_0 = (const float*)d_in[4];
    const float* b_ih_0 = (const float*)d_in[5];
    const float* b_hh_0 = (const float*)d_in[6];
    const float* w_ih_1 = (const float*)d_in[7];
    const float* w_hh_1 = (const float*)d_in[8];
    const float* b_ih_1 = (const float*)d_in[9];
    const float* b_hh_1 = (const float*)d_in[10];
    (void)in_sizes; (void)n_in; (void)out_size;

    float* out = (float*)d_out;
    float* res = out;                                  // [65536, 512]
    float* lh  = out + (size_t)MROWS * HHH;            // [2, 64, 512]
    float* lc  = lh + 2 * BB * HHH;                    // [2, 64, 512]

    cudaFuncSetAttribute(lstm_mma_kernel,
                         cudaFuncAttributeMaxDynamicSharedMemorySize, SMEMT);

    // precision-split pre-pass
    cvt_split<<<(MROWS * IIK / 4 + 255) / 256, 256>>>(x, MROWS * IIK / 4, 0);
    cvt_split<<<(G4 * IIK / 4 + 255) / 256, 256>>>(w_ih_0, G4 * IIK / 4, 1);
    cvt_split<<<(G4 * IIK / 4 + 255) / 256, 256>>>(w_ih_1, G4 * IIK / 4, 2);

    // hh precompute (tiled GEMM, both layers in one launch)
    dim3 hgrid(G4 / 64, 2);
    hh_kernel<<<hgrid, 256>>>(h0, w_hh_0, w_hh_1, b_ih_0, b_hh_0, b_ih_1, b_hh_1);

    // HMMA layers
    dim3 ggrid(HHH / TNH, MROWS / TM);   // (16, 512)
    lstm_mma_kernel<<<ggrid, 256, SMEMT>>>(c0, res, lh, lc, 0);
    lstm_mma_kernel<<<ggrid, 256, SMEMT>>>(c0, res, lh, lc, 1);
}

// round 5
// speedup vs baseline: 3.7397x; 1.3374x over previous
#include <cuda_runtime.h>
#include <cuda_fp16.h>
#include <cstdint>

// ---------------- problem dims ----------------
#define MROWS 65536     // T*B
#define IIK   512       // K
#define G4    2048      // 4*H
#define BB    64        // batch
#define HHH   512       // H

// ---------------- tiling ----------------
#define TM   128        // M rows per CTA
#define TNH  32         // hy cols per CTA -> 128 gate cols
#define KC   32         // K chunk
#define NIT  16         // 512/32
#define NSTAGE 3

// smem stage: A_hi(10240) A_lo(10240) B_hi(10240) = 30720 B
// rows: 32 fp16 = 64 B data + 16 B pad = 80 B stride
#define STG   30720
#define SMEMT (NSTAGE*STG)   // 92160; epilogue reuses as 128x132 f32 (67584 B)

// ---------------- device scratch (no runtime alloc) ----------------
__device__ __align__(16) __half g_A0_hi[(size_t)MROWS * IIK];
__device__ __align__(16) __half g_A0_lo[(size_t)MROWS * IIK];
__device__ __align__(16) __half g_A1_hi[(size_t)MROWS * IIK];
__device__ __align__(16) __half g_A1_lo[(size_t)MROWS * IIK];
__device__ __align__(16) __half g_W[2][G4 * IIK];
__device__ float g_hh[2][BB][G4];

// ---------------- asm helpers (plain sm_80/90 PTX only) ----------------
__device__ __forceinline__ uint32_t smem_to_u32(const void* p) {
    uint32_t a;
    asm("{ .reg .u64 t; cvta.to.shared.u64 t, %1; cvt.u32.u64 %0, t; }"
        : "=r"(a) : "l"(p));
    return a;
}
#define CP_ASYNC16(s, g) \
    asm volatile("cp.async.cg.shared.global [%0], [%1], 16;" :: "r"(s), "l"(g))
#define CP_COMMIT() asm volatile("cp.async.commit_group;" ::: "memory")
#define CP_WAIT2()  asm volatile("cp.async.wait_group 2;" ::: "memory")
#define CP_WAIT1()  asm volatile("cp.async.wait_group 1;" ::: "memory")
#define CP_WAIT0()  asm volatile("cp.async.wait_group 0;" ::: "memory")

#define LDSM4(r, addr) \
    asm volatile("ldmatrix.sync.aligned.m8n8.x4.shared.b16 {%0,%1,%2,%3}, [%4];" \
        : "=r"((r)[0]), "=r"((r)[1]), "=r"((r)[2]), "=r"((r)[3]) : "r"(addr))

__device__ __forceinline__ void mma_f16(float* c, const unsigned* a, const unsigned* b) {
    asm volatile(
        "mma.sync.aligned.m16n8k16.row.col.f32.f16.f16.f32 "
        "{%0,%1,%2,%3}, {%4,%5,%6,%7}, {%8,%9}, {%0,%1,%2,%3};"
        : "+f"(c[0]), "+f"(c[1]), "+f"(c[2]), "+f"(c[3])
        : "r"(a[0]), "r"(a[1]), "r"(a[2]), "r"(a[3]), "r"(b[0]), "r"(b[1]));
}

// ---------------- activations ----------------
__device__ __forceinline__ float sigf(float x) {
    return __fdividef(1.0f, 1.0f + __expf(-x));
}
__device__ __forceinline__ float tanhf_(float x) {
    return 2.0f * sigf(2.0f * x) - 1.0f;
}

// ---------------------------------------------------------------------------
// splitters.  cvt_split: fp32 -> fp16 hi + fp16 lo (x -> A0)
//             cvt_w:     fp32 -> fp16 (weights, single)
// ---------------------------------------------------------------------------
__global__ void cvt_split(const float* __restrict__ src, int n4) {
    int i = blockIdx.x * blockDim.x + threadIdx.x;
    if (i >= n4) return;
    float4 v = ((const float4*)src)[i];
    __half hx = __float2half(v.x), hy = __float2half(v.y);
    __half hz = __float2half(v.z), hw = __float2half(v.w);
    __half lx = __float2half(v.x - __half2float(hx));
    __half ly = __float2half(v.y - __half2float(hy));
    __half lz = __float2half(v.z - __half2float(hz));
    __half lw = __float2half(v.w - __half2float(hw));
    ((__half2*)g_A0_hi)[2*i]   = __half2(hx, hy);
    ((__half2*)g_A0_hi)[2*i+1] = __half2(hz, hw);
    ((__half2*)g_A0_lo)[2*i]   = __half2(lx, ly);
    ((__half2*)g_A0_lo)[2*i+1] = __half2(lz, lw);
}

__global__ void cvt_w(const float* __restrict__ w0, const float* __restrict__ w1, int n4) {
    int i = blockIdx.x * blockDim.x + threadIdx.x;
    if (i >= n4) return;
    float4 a = ((const float4*)w0)[i];
    float4 b = ((const float4*)w1)[i];
    ((__half2*)g_W[0])[2*i]   = __half2(__float2half(a.x), __float2half(a.y));
    ((__half2*)g_W[0])[2*i+1] = __half2(__float2half(a.z), __float2half(a.w));
    ((__half2*)g_W[1])[2*i]   = __half2(__float2half(b.x), __float2half(b.y));
    ((__half2*)g_W[1])[2*i+1] = __half2(__float2half(b.z), __float2half(b.w));
}

// ---------------------------------------------------------------------------
// hh[l][b][g] = h0[l][b] . w_hh[g] + b_ih[g] + b_hh[g]   (fp32 tiled GEMM)
// ---------------------------------------------------------------------------
__global__ void __launch_bounds__(256)
hh_kernel(const float* __restrict__ h0,
          const float* __restrict__ w_hh_0, const float* __restrict__ w_hh_1,
          const float* __restrict__ b_ih_0, const float* __restrict__ b_hh_0,
          const float* __restrict__ b_ih_1, const float* __restrict__ b_hh_1) {
    const int layer = blockIdx.y;
    const int g0 = blockIdx.x * 64;
    const float* __restrict__ w  = layer ? w_hh_1 : w_hh_0;
    const float* __restrict__ bi = layer ? b_ih_1 : b_ih_0;
    const float* __restrict__ bh = layer ? b_hh_1 : b_hh_0;

    __shared__ __align__(16) float As[KC][68];
    __shared__ __align__(16) float Bs[KC][68];

    const int tid = threadIdx.x;
    const int tx = tid & 15;
    const int ty = tid >> 4;
    const int lr  = tid >> 3;
    const int lk4 = tid & 7;

    float acc[4][4];
#pragma unroll
    for (int i = 0; i < 4; i++)
#pragma unroll
        for (int j = 0; j < 4; j++) acc[i][j] = 0.0f;

    for (int k0 = 0; k0 < IIK; k0 += KC) {
#pragma unroll
        for (int rep = 0; rep < 2; ++rep) {
            const int row = lr + rep * 32;
            float4 av = *(const float4*)(h0 + ((size_t)layer * BB + row) * IIK + k0 + lk4 * 4);
            As[lk4 * 4 + 0][row] = av.x;
            As[lk4 * 4 + 1][row] = av.y;
            As[lk4 * 4 + 2][row] = av.z;
            As[lk4 * 4 + 3][row] = av.w;
            float4 bv = *(const float4*)(w + (size_t)(g0 + row) * IIK + k0 + lk4 * 4);
            Bs[lk4 * 4 + 0][row] = bv.x;
            Bs[lk4 * 4 + 1][row] = bv.y;
            Bs[lk4 * 4 + 2][row] = bv.z;
            Bs[lk4 * 4 + 3][row] = bv.w;
        }
        __syncthreads();
#pragma unroll
        for (int k = 0; k < KC; ++k) {
            float a_[4], b_[4];
#pragma unroll
            for (int i = 0; i < 4; i++) a_[i] = As[k][ty * 4 + i];
#pragma unroll
            for (int j = 0; j < 4; j++) b_[j] = Bs[k][tx * 4 + j];
#pragma unroll
            for (int i = 0; i < 4; i++)
#pragma unroll
                for (int j = 0; j < 4; j++) acc[i][j] = fmaf(a_[i], b_[j], acc[i][j]);
        }
        __syncthreads();
    }
#pragma unroll
    for (int i = 0; i < 4; i++) {
        const int b = ty * 4 + i;
#pragma unroll
        for (int j = 0; j < 4; j++) {
            const int g = g0 + tx * 4 + j;
            g_hh[layer][b][g] = acc[i][j] + bi[g] + bh[g];
        }
    }
}

// ---------------------------------------------------------------------------
// Main HMMA LSTM layer kernel.  grid (16, 512), 256 threads, 2 CTAs/SM,
// 3-stage cp.async pipeline.  2 MMA terms: Ah*W + Al*W.
// ---------------------------------------------------------------------------
__global__ void __launch_bounds__(256, 2)
lstm_mma_kernel(const float* __restrict__ c0,
                float* __restrict__ res,
                float* __restrict__ lh,
                float* __restrict__ lc,
                int layer) {
    extern __shared__ __align__(16) char sm[];
    const uint32_t smem_u32 = smem_to_u32(sm);
    const int tid  = threadIdx.x;
    const int wid  = tid >> 5;
    const int lane = tid & 31;
    const int n0h  = blockIdx.x * TNH;
    const int m0   = blockIdx.y * TM;

    const __half* __restrict__ Ah = layer ? g_A1_hi : g_A0_hi;
    const __half* __restrict__ Al = layer ? g_A1_lo : g_A0_lo;
    const __half* __restrict__ Wp = g_W[layer];
    const float* __restrict__ hh_l = &g_hh[layer][0][0];
    const float* __restrict__ c0_l = c0 + (size_t)layer * BB * HHH;
    float* __restrict__ lasth = lh + (size_t)layer * BB * HHH;
    float* __restrict__ lastc = lc + (size_t)layer * BB * HHH;

    // loader invariants
    const int rA  = tid >> 2;     // rows rA and rA+64
    const int kc8 = tid & 3;      // 16B granule along k

    // ldmatrix invariants
    const int wm = wid & 3;       // M sub-tile (32 rows)
    const int wn = wid >> 2;      // N half (64 gate cols)
    const uint32_t aRowOff = (uint32_t)(lane & 15) * 80;
    const uint32_t aKoff   = (uint32_t)((lane >> 4) & 1) * 16;
    const uint32_t bRowOff = (uint32_t)(((lane >> 4) & 1) * 8 + (lane & 7)) * 80;
    const uint32_t bKoff   = (uint32_t)((lane >> 3) & 1) * 16;

    float acc[2][8][4];
#pragma unroll
    for (int mt = 0; mt < 2; ++mt)
#pragma unroll
        for (int nb = 0; nb < 8; ++nb)
#pragma unroll
            for (int q = 0; q < 4; ++q) acc[mt][nb][q] = 0.0f;

#define LOAD_STAGE(CHUNK)                                                      \
    do {                                                                       \
        const int _k0 = (CHUNK) * KC;                                          \
        const uint32_t _sb = smem_u32 + ((CHUNK) % NSTAGE) * STG;              \
        _Pragma("unroll")                                                      \
        for (int rep = 0; rep < 2; ++rep) {                                    \
            const int row = rA + rep * 64;                                     \
            const uint32_t so = _sb + row * 80 + kc8 * 16;                     \
            const size_t ga = (size_t)(m0 + row) * IIK + _k0 + kc8 * 8;        \
            CP_ASYNC16(so,          Ah + ga);                                  \
            CP_ASYNC16(so + 10240,  Al + ga);                                  \
            const int wrow = (row & 3) * 512 + n0h + (row >> 2);               \
            const size_t gb = (size_t)wrow * IIK + _k0 + kc8 * 8;              \
            CP_ASYNC16(so + 20480,  Wp + gb);                                  \
        }                                                                      \
        CP_COMMIT();                                                           \
    } while (0)

    LOAD_STAGE(0);
    LOAD_STAGE(1);

    for (int it = 0; it < NIT; ++it) {
        if (it + 2 < NIT) { LOAD_STAGE(it + 2); CP_WAIT2(); }
        else if (it + 1 < NIT) { CP_WAIT1(); }
        else { CP_WAIT0(); }
        __syncthreads();

        const uint32_t sb = smem_u32 + (it % NSTAGE) * STG;
#pragma unroll
        for (int ks = 0; ks < 2; ++ks) {
            unsigned ah[2][4], al[2][4];
#pragma unroll
            for (int mt = 0; mt < 2; ++mt) {
                uint32_t aa = sb + (uint32_t)(wm * 32 + mt * 16) * 80
                              + aRowOff + ks * 32 + aKoff;
                LDSM4(ah[mt], aa);
                LDSM4(al[mt], aa + 10240);
            }
            unsigned bh[4][4];
#pragma unroll
            for (int p = 0; p < 4; ++p) {
                uint32_t ba = sb + 20480 + (uint32_t)(wn * 64 + p * 16) * 80
                              + bRowOff + ks * 32 + bKoff;
                LDSM4(bh[p], ba);
            }
#pragma unroll
            for (int mt = 0; mt < 2; ++mt)
#pragma unroll
                for (int p = 0; p < 4; ++p) {
                    mma_f16(acc[mt][2*p],   ah[mt], &bh[p][0]);
                    mma_f16(acc[mt][2*p+1], ah[mt], &bh[p][2]);
                    mma_f16(acc[mt][2*p],   al[mt], &bh[p][0]);
                    mma_f16(acc[mt][2*p+1], al[mt], &bh[p][2]);
                }
        }
        __syncthreads();
    }

    // ---- epilogue: dump gate tile (128 x 128 f32, stride 132) into smem ----
    float* Gs = (float*)sm;
#pragma unroll
    for (int mt = 0; mt < 2; ++mt) {
        const int r0 = wm * 32 + mt * 16 + (lane >> 2);
#pragma unroll
        for (int nb = 0; nb < 8; ++nb) {
            const int cb = wn * 64 + nb * 8 + (lane & 3) * 2;
            Gs[r0 * 132 + cb]           = acc[mt][nb][0];
            Gs[r0 * 132 + cb + 1]       = acc[mt][nb][1];
            Gs[(r0 + 8) * 132 + cb]     = acc[mt][nb][2];
            Gs[(r0 + 8) * 132 + cb + 1] = acc[mt][nb][3];
        }
    }
    __syncthreads();

    // ---- fused LSTM pointwise: 128 rows x 16 col-pairs per CTA ----
    for (int e = tid; e < TM * (TNH / 2); e += 256) {
        const int row = e >> 4;
        const int c2  = e & 15;
        const int m   = m0 + row;
        const int b   = m & (BB - 1);
        const int nh  = n0h + c2 * 2;
        const float* hhb = hh_l + (size_t)b * G4;
        float hy2[2], cy2[2];
#pragma unroll
        for (int u = 0; u < 2; ++u) {
            const int col = c2 * 2 + u;
            float ig = Gs[row * 132 + col * 4 + 0] + hhb[nh + u];
            float fg = Gs[row * 132 + col * 4 + 1] + hhb[512 + nh + u];
            float gg = Gs[row * 132 + col * 4 + 2] + hhb[1024 + nh + u];
            float og = Gs[row * 132 + col * 4 + 3] + hhb[1536 + nh + u];
            float cy = sigf(fg) * c0_l[(size_t)b * HHH + nh + u] + sigf(ig) * tanhf_(gg);
            cy2[u] = cy;
            hy2[u] = sigf(og) * tanhf_(cy);
        }
        if (layer == 0) {
            __half h0h = __float2half(hy2[0]);
            __half h1h = __float2half(hy2[1]);
            __half l0h = __float2half(hy2[0] - __half2float(h0h));
            __half l1h = __float2half(hy2[1] - __half2float(h1h));
            *(__half2*)(g_A1_hi + (size_t)m * HHH + nh) = __half2(h0h, h1h);
            *(__half2*)(g_A1_lo + (size_t)m * HHH + nh) = __half2(l0h, l1h);
        } else {
            *(float2*)(res + (size_t)m * HHH + nh) = make_float2(hy2[0], hy2[1]);
        }
        if (m >= MROWS - BB) {
            *(float2*)(lasth + (size_t)b * HHH + nh) = make_float2(hy2[0], hy2[1]);
            *(float2*)(lastc + (size_t)b * HHH + nh) = make_float2(cy2[0], cy2[1]);
        }
    }
}

// ---------------------------------------------------------------------------
extern "C" void kernel_launch(void* const* d_in, const int* in_sizes, int n_in,
                              void* d_out, int out_size) {
    const float* x      = (const float*)d_in[0];
    const float* h0     = (const float*)d_in[1];
    const float* c0     = (const float*)d_in[2];
    const float* w_ih_0 = (const float*)d_in[3];
    const float* w_hh_0 = (const float*)d_in[4];
    const float* b_ih_0 = (const float*)d_in[5];
    const float* b_hh_0 = (const float*)d_in[6];
    const float* w_ih_1 = (const float*)d_in[7];
    const float* w_hh_1 = (const float*)d_in[8];
    const float* b_ih_1 = (const float*)d_in[9];
    const float* b_hh_1 = (const float*)d_in[10];
    (void)in_sizes; (void)n_in; (void)out_size;

    float* out = (float*)d_out;
    float* res = out;                                  // [65536, 512]
    float* lh  = out + (size_t)MROWS * HHH;            // [2, 64, 512]
    float* lc  = lh + 2 * BB * HHH;                    // [2, 64, 512]

    cudaFuncSetAttribute(lstm_mma_kernel,
                         cudaFuncAttributeMaxDynamicSharedMemorySize, SMEMT);

    // precision pre-pass
    cvt_split<<<(MROWS * IIK / 4 + 255) / 256, 256>>>(x, MROWS * IIK / 4);
    cvt_w<<<(G4 * IIK / 4 + 255) / 256, 256>>>(w_ih_0, w_ih_1, G4 * IIK / 4);

    // hh precompute (tiled GEMM, both layers in one launch)
    dim3 hgrid(G4 / 64, 2);
    hh_kernel<<<hgrid, 256>>>(h0, w_hh_0, w_hh_1, b_ih_0, b_hh_0, b_ih_1, b_hh_1);

    // HMMA layers
    dim3 ggrid(HHH / TNH, MROWS / TM);   // (16, 512)
    lstm_mma_kernel<<<ggrid, 256, SMEMT>>>(c0, res, lh, lc, 0);
    lstm_mma_kernel<<<ggrid, 256, SMEMT>>>(c0, res, lh, lc, 1);
}

// round 6
// speedup vs baseline: 5.8058x; 1.5525x over previous
#include <cuda_runtime.h>
#include <cuda_fp16.h>
#include <cstdint>

// ---------------- problem dims ----------------
#define MROWS 65536     // T*B
#define IIK   512       // K
#define G4    2048      // 4*H
#define BB    64        // batch
#define HHH   512       // H

// ---------------- tiling ----------------
#define TM   128        // M rows per CTA
#define TNH  32         // hy cols per CTA -> 128 gate cols
#define KC   64         // K chunk per iteration
#define NIT  8          // 512/64
#define NSTAGE 3

// stage: A (128 rows x 144B) + B (128 rows x 144B); 64 fp16 = 128 B data + 16 pad
#define ROWSTR 144
#define B_OFF  18432               // 128*144
#define STG    36864               // 2*18432
#define SMEMT  (NSTAGE*STG)        // 110592; epilogue reuses 128x132 f32 (67584)

// ---------------- device scratch (no runtime alloc) ----------------
__device__ __align__(16) __half g_A0[(size_t)MROWS * IIK];
__device__ __align__(16) __half g_A1[(size_t)MROWS * IIK];
__device__ __align__(16) __half g_W[2][G4 * IIK];
__device__ float g_hh[2][BB][G4];

// ---------------- asm helpers (plain sm_80/90 PTX only) ----------------
__device__ __forceinline__ uint32_t smem_to_u32(const void* p) {
    uint32_t a;
    asm("{ .reg .u64 t; cvta.to.shared.u64 t, %1; cvt.u32.u64 %0, t; }"
        : "=r"(a) : "l"(p));
    return a;
}
#define CP_ASYNC16(s, g) \
    asm volatile("cp.async.cg.shared.global [%0], [%1], 16;" :: "r"(s), "l"(g))
#define CP_COMMIT() asm volatile("cp.async.commit_group;" ::: "memory")
#define CP_WAIT2()  asm volatile("cp.async.wait_group 2;" ::: "memory")
#define CP_WAIT1()  asm volatile("cp.async.wait_group 1;" ::: "memory")
#define CP_WAIT0()  asm volatile("cp.async.wait_group 0;" ::: "memory")

#define LDSM4(r, addr) \
    asm volatile("ldmatrix.sync.aligned.m8n8.x4.shared.b16 {%0,%1,%2,%3}, [%4];" \
        : "=r"((r)[0]), "=r"((r)[1]), "=r"((r)[2]), "=r"((r)[3]) : "r"(addr))

__device__ __forceinline__ void mma_f16(float* c, const unsigned* a, const unsigned* b) {
    asm volatile(
        "mma.sync.aligned.m16n8k16.row.col.f32.f16.f16.f32 "
        "{%0,%1,%2,%3}, {%4,%5,%6,%7}, {%8,%9}, {%0,%1,%2,%3};"
        : "+f"(c[0]), "+f"(c[1]), "+f"(c[2]), "+f"(c[3])
        : "r"(a[0]), "r"(a[1]), "r"(a[2]), "r"(a[3]), "r"(b[0]), "r"(b[1]));
}

// ---------------- activations ----------------
__device__ __forceinline__ float sigf(float x) {
    return __fdividef(1.0f, 1.0f + __expf(-x));
}
__device__ __forceinline__ float tanhf_(float x) {
    return 2.0f * sigf(2.0f * x) - 1.0f;
}

// ---------------------------------------------------------------------------
// converters: x -> fp16, weights -> fp16
// ---------------------------------------------------------------------------
__global__ void cvt_x(const float* __restrict__ src, int n4) {
    int i = blockIdx.x * blockDim.x + threadIdx.x;
    if (i >= n4) return;
    float4 v = ((const float4*)src)[i];
    ((__half2*)g_A0)[2*i]   = __half2(__float2half(v.x), __float2half(v.y));
    ((__half2*)g_A0)[2*i+1] = __half2(__float2half(v.z), __float2half(v.w));
}

__global__ void cvt_w(const float* __restrict__ w0, const float* __restrict__ w1, int n4) {
    int i = blockIdx.x * blockDim.x + threadIdx.x;
    if (i >= n4) return;
    float4 a = ((const float4*)w0)[i];
    float4 b = ((const float4*)w1)[i];
    ((__half2*)g_W[0])[2*i]   = __half2(__float2half(a.x), __float2half(a.y));
    ((__half2*)g_W[0])[2*i+1] = __half2(__float2half(a.z), __float2half(a.w));
    ((__half2*)g_W[1])[2*i]   = __half2(__float2half(b.x), __float2half(b.y));
    ((__half2*)g_W[1])[2*i+1] = __half2(__float2half(b.z), __float2half(b.w));
}

// ---------------------------------------------------------------------------
// hh[l][b][g] = h0[l][b] . w_hh[g] + b_ih[g] + b_hh[g]   (fp32 tiled GEMM)
// ---------------------------------------------------------------------------
__global__ void __launch_bounds__(256)
hh_kernel(const float* __restrict__ h0,
          const float* __restrict__ w_hh_0, const float* __restrict__ w_hh_1,
          const float* __restrict__ b_ih_0, const float* __restrict__ b_hh_0,
          const float* __restrict__ b_ih_1, const float* __restrict__ b_hh_1) {
    const int layer = blockIdx.y;
    const int g0 = blockIdx.x * 64;
    const float* __restrict__ w  = layer ? w_hh_1 : w_hh_0;
    const float* __restrict__ bi = layer ? b_ih_1 : b_ih_0;
    const float* __restrict__ bh = layer ? b_hh_1 : b_hh_0;

    __shared__ __align__(16) float As[32][68];
    __shared__ __align__(16) float Bs[32][68];

    const int tid = threadIdx.x;
    const int tx = tid & 15;
    const int ty = tid >> 4;
    const int lr  = tid >> 3;
    const int lk4 = tid & 7;

    float acc[4][4];
#pragma unroll
    for (int i = 0; i < 4; i++)
#pragma unroll
        for (int j = 0; j < 4; j++) acc[i][j] = 0.0f;

    for (int k0 = 0; k0 < IIK; k0 += 32) {
#pragma unroll
        for (int rep = 0; rep < 2; ++rep) {
            const int row = lr + rep * 32;
            float4 av = *(const float4*)(h0 + ((size_t)layer * BB + row) * IIK + k0 + lk4 * 4);
            As[lk4 * 4 + 0][row] = av.x;
            As[lk4 * 4 + 1][row] = av.y;
            As[lk4 * 4 + 2][row] = av.z;
            As[lk4 * 4 + 3][row] = av.w;
            float4 bv = *(const float4*)(w + (size_t)(g0 + row) * IIK + k0 + lk4 * 4);
            Bs[lk4 * 4 + 0][row] = bv.x;
            Bs[lk4 * 4 + 1][row] = bv.y;
            Bs[lk4 * 4 + 2][row] = bv.z;
            Bs[lk4 * 4 + 3][row] = bv.w;
        }
        __syncthreads();
#pragma unroll
        for (int k = 0; k < 32; ++k) {
            float a_[4], b_[4];
#pragma unroll
            for (int i = 0; i < 4; i++) a_[i] = As[k][ty * 4 + i];
#pragma unroll
            for (int j = 0; j < 4; j++) b_[j] = Bs[k][tx * 4 + j];
#pragma unroll
            for (int i = 0; i < 4; i++)
#pragma unroll
                for (int j = 0; j < 4; j++) acc[i][j] = fmaf(a_[i], b_[j], acc[i][j]);
        }
        __syncthreads();
    }
#pragma unroll
    for (int i = 0; i < 4; i++) {
        const int b = ty * 4 + i;
#pragma unroll
        for (int j = 0; j < 4; j++) {
            const int g = g0 + tx * 4 + j;
            g_hh[layer][b][g] = acc[i][j] + bi[g] + bh[g];
        }
    }
}

// ---------------------------------------------------------------------------
// Main HMMA LSTM layer kernel.  grid (16, 512), 256 threads, 2 CTAs/SM,
// 3-stage cp.async pipeline, KC=64, single fp16 term.
// Gate-interleaved B rows: smem B row n <-> w_ih row (n%4)*512 + n0h + n/4.
// ---------------------------------------------------------------------------
__global__ void __launch_bounds__(256, 2)
lstm_mma_kernel(const float* __restrict__ c0,
                float* __restrict__ res,
                float* __restrict__ lh,
                float* __restrict__ lc,
                int layer) {
    extern __shared__ __align__(16) char sm[];
    const uint32_t smem_u32 = smem_to_u32(sm);
    const int tid  = threadIdx.x;
    const int wid  = tid >> 5;
    const int lane = tid & 31;
    const int n0h  = blockIdx.x * TNH;
    const int m0   = blockIdx.y * TM;

    const __half* __restrict__ Ax = layer ? g_A1 : g_A0;
    const __half* __restrict__ Wp = g_W[layer];
    const float* __restrict__ hh_l = &g_hh[layer][0][0];
    const float* __restrict__ c0_l = c0 + (size_t)layer * BB * HHH;
    float* __restrict__ lasth = lh + (size_t)layer * BB * HHH;
    float* __restrict__ lastc = lc + (size_t)layer * BB * HHH;

    // loader invariants: rows tid>>2 (+64), two 4-granule halves per row
    const int rA  = tid >> 2;
    const int gc0 = tid & 3;

    // ldmatrix invariants
    const int wm = wid & 3;       // M sub-tile (32 rows)
    const int wn = wid >> 2;      // N half (64 gate cols)
    const uint32_t aRowOff = (uint32_t)(lane & 15) * ROWSTR;
    const uint32_t aKoff   = (uint32_t)((lane >> 4) & 1) * 16;
    const uint32_t bRowOff = (uint32_t)(((lane >> 4) & 1) * 8 + (lane & 7)) * ROWSTR;
    const uint32_t bKoff   = (uint32_t)((lane >> 3) & 1) * 16;

    float acc[2][8][4];
#pragma unroll
    for (int mt = 0; mt < 2; ++mt)
#pragma unroll
        for (int nb = 0; nb < 8; ++nb)
#pragma unroll
            for (int q = 0; q < 4; ++q) acc[mt][nb][q] = 0.0f;

#define LOAD_STAGE(CHUNK)                                                      \
    do {                                                                       \
        const int _k0 = (CHUNK) * KC;                                          \
        const uint32_t _sb = smem_u32 + ((CHUNK) % NSTAGE) * STG;              \
        _Pragma("unroll")                                                      \
        for (int rep = 0; rep < 2; ++rep) {                                    \
            const int row = rA + rep * 64;                                     \
            const int wrow = (row & 3) * 512 + n0h + (row >> 2);               \
            _Pragma("unroll")                                                  \
            for (int hf = 0; hf < 2; ++hf) {                                   \
                const int gc = gc0 + hf * 4;                                   \
                const uint32_t so = _sb + row * ROWSTR + gc * 16;              \
                CP_ASYNC16(so,         Ax + (size_t)(m0 + row) * IIK + _k0 + gc * 8); \
                CP_ASYNC16(so + B_OFF, Wp + (size_t)wrow * IIK + _k0 + gc * 8);       \
            }                                                                  \
        }                                                                      \
        CP_COMMIT();                                                           \
    } while (0)

    LOAD_STAGE(0);
    LOAD_STAGE(1);

    for (int it = 0; it < NIT; ++it) {
        if (it + 2 < NIT) { LOAD_STAGE(it + 2); CP_WAIT2(); }
        else if (it + 1 < NIT) { CP_WAIT1(); }
        else { CP_WAIT0(); }
        __syncthreads();

        const uint32_t sb = smem_u32 + (it % NSTAGE) * STG;
#pragma unroll
        for (int ks = 0; ks < 4; ++ks) {
            unsigned ah[2][4];
#pragma unroll
            for (int mt = 0; mt < 2; ++mt) {
                uint32_t aa = sb + (uint32_t)(wm * 32 + mt * 16) * ROWSTR
                              + aRowOff + ks * 32 + aKoff;
                LDSM4(ah[mt], aa);
            }
            unsigned bh[4][4];
#pragma unroll
            for (int p = 0; p < 4; ++p) {
                uint32_t ba = sb + B_OFF + (uint32_t)(wn * 64 + p * 16) * ROWSTR
                              + bRowOff + ks * 32 + bKoff;
                LDSM4(bh[p], ba);
            }
#pragma unroll
            for (int mt = 0; mt < 2; ++mt)
#pragma unroll
                for (int p = 0; p < 4; ++p) {
                    mma_f16(acc[mt][2*p],   ah[mt], &bh[p][0]);
                    mma_f16(acc[mt][2*p+1], ah[mt], &bh[p][2]);
                }
        }
        __syncthreads();
    }

    // ---- epilogue: dump gate tile (128 x 128 f32, stride 132) into smem ----
    float* Gs = (float*)sm;
#pragma unroll
    for (int mt = 0; mt < 2; ++mt) {
        const int r0 = wm * 32 + mt * 16 + (lane >> 2);
#pragma unroll
        for (int nb = 0; nb < 8; ++nb) {
            const int cb = wn * 64 + nb * 8 + (lane & 3) * 2;
            Gs[r0 * 132 + cb]           = acc[mt][nb][0];
            Gs[r0 * 132 + cb + 1]       = acc[mt][nb][1];
            Gs[(r0 + 8) * 132 + cb]     = acc[mt][nb][2];
            Gs[(r0 + 8) * 132 + cb + 1] = acc[mt][nb][3];
        }
    }
    __syncthreads();

    // ---- fused LSTM pointwise: 128 rows x 16 col-pairs per CTA ----
    for (int e = tid; e < TM * (TNH / 2); e += 256) {
        const int row = e >> 4;
        const int c2  = e & 15;
        const int m   = m0 + row;
        const int b   = m & (BB - 1);
        const int nh  = n0h + c2 * 2;
        const float* hhb = hh_l + (size_t)b * G4;
        float hy2[2], cy2[2];
#pragma unroll
        for (int u = 0; u < 2; ++u) {
            const int col = c2 * 2 + u;
            float ig = Gs[row * 132 + col * 4 + 0] + hhb[nh + u];
            float fg = Gs[row * 132 + col * 4 + 1] + hhb[512 + nh + u];
            float gg = Gs[row * 132 + col * 4 + 2] + hhb[1024 + nh + u];
            float og = Gs[row * 132 + col * 4 + 3] + hhb[1536 + nh + u];
            float cy = sigf(fg) * c0_l[(size_t)b * HHH + nh + u] + sigf(ig) * tanhf_(gg);
            cy2[u] = cy;
            hy2[u] = sigf(og) * tanhf_(cy);
        }
        if (layer == 0) {
            *(__half2*)(g_A1 + (size_t)m * HHH + nh) =
                __half2(__float2half(hy2[0]), __float2half(hy2[1]));
        } else {
            *(float2*)(res + (size_t)m * HHH + nh) = make_float2(hy2[0], hy2[1]);
        }
        if (m >= MROWS - BB) {
            *(float2*)(lasth + (size_t)b * HHH + nh) = make_float2(hy2[0], hy2[1]);
            *(float2*)(lastc + (size_t)b * HHH + nh) = make_float2(cy2[0], cy2[1]);
        }
    }
}

// ---------------------------------------------------------------------------
extern "C" void kernel_launch(void* const* d_in, const int* in_sizes, int n_in,
                              void* d_out, int out_size) {
    const float* x      = (const float*)d_in[0];
    const float* h0     = (const float*)d_in[1];
    const float* c0     = (const float*)d_in[2];
    const float* w_ih_0 = (const float*)d_in[3];
    const float* w_hh_0 = (const float*)d_in[4];
    const float* b_ih_0 = (const float*)d_in[5];
    const float* b_hh_0 = (const float*)d_in[6];
    const float* w_ih_1 = (const float*)d_in[7];
    const float* w_hh_1 = (const float*)d_in[8];
    const float* b_ih_1 = (const float*)d_in[9];
    const float* b_hh_1 = (const float*)d_in[10];
    (void)in_sizes; (void)n_in; (void)out_size;

    float* out = (float*)d_out;
    float* res = out;                                  // [65536, 512]
    float* lh  = out + (size_t)MROWS * HHH;            // [2, 64, 512]
    float* lc  = lh + 2 * BB * HHH;                    // [2, 64, 512]

    cudaFuncSetAttribute(lstm_mma_kernel,
                         cudaFuncAttributeMaxDynamicSharedMemorySize, SMEMT);

    // precision pre-pass
    cvt_x<<<(MROWS * IIK / 4 + 255) / 256, 256>>>(x, MROWS * IIK / 4);
    cvt_w<<<(G4 * IIK / 4 + 255) / 256, 256>>>(w_ih_0, w_ih_1, G4 * IIK / 4);

    // hh precompute (tiled GEMM, both layers in one launch)
    dim3 hgrid(G4 / 64, 2);
    hh_kernel<<<hgrid, 256>>>(h0, w_hh_0, w_hh_1, b_ih_0, b_hh_0, b_ih_1, b_hh_1);

    // HMMA layers
    dim3 ggrid(HHH / TNH, MROWS / TM);   // (16, 512)
    lstm_mma_kernel<<<ggrid, 256, SMEMT>>>(c0, res, lh, lc, 0);
    lstm_mma_kernel<<<ggrid, 256, SMEMT>>>(c0, res, lh, lc, 1);
}